// round 7
// baseline (speedup 1.0000x reference)
#include <cuda_runtime.h>
#include <cstdint>

#define DIN  1024
#define DH   512
#define NB   8192
#define DOUT 512

#define MT 32            // rows per tile in recurrent kernel
#define NT 512           // threads per CTA (16 warps -> 4 per SMSP)
#define KC 8             // k-chunk staged in smem
#define NCHUNK (DH / KC) // 64
// smem: hh + xeb + h (each MT*DH f32) + W double buffer (2*KC*DH f32)
#define REC_SMEM_BYTES ((3 * MT * DH + 2 * KC * DH) * 4)  // 229376

typedef unsigned long long ull;

// ---------------- scratch (static device allocations: allowed) ----------------
__device__ float g_sigma;
__device__ __align__(16) float g_Wt[DH * DH];     // Wt[k][n] = W[n][k]/sigma
__device__ __align__(16) float g_Wet[DIN * DH];   // Wet[d][j] = We[j][d]
__device__ __align__(16) float g_Wht[DH * DOUT];  // Wht[k][o] = Wh[o][k]
__device__ __align__(16) float g_xemb[NB * DH];
__device__ __align__(16) float g_h[NB * DH];

// ---------------- helpers ----------------
__device__ __forceinline__ ull pk2(float x, float y) {
    ull r;
    asm("mov.b64 %0, {%1,%2};" : "=l"(r) : "f"(x), "f"(y));
    return r;
}
__device__ __forceinline__ void upk2(ull a, float& x, float& y) {
    asm("mov.b64 {%0,%1}, %2;" : "=f"(x), "=f"(y) : "l"(a));
}
// packed fp32x2 FMA (Blackwell): 2x FFMA throughput
__device__ __forceinline__ ull fma2(ull a, ull b, ull c) {
    ull d;
    asm("fma.rn.f32x2 %0, %1, %2, %3;" : "=l"(d) : "l"(a), "l"(b), "l"(c));
    return d;
}
// accurate-enough tanh (~1e-6), immune to -use_fast_math lowering of tanhf
__device__ __forceinline__ float fast_tanh(float x) {
    float a = fabsf(x);
    float e = exp2f(-2.8853900817779268f * a);  // exp(-2a)
    float r = __fdividef(1.0f - e, 1.0f + e);
    return copysignf(r, x);
}

// ---------------- kernel 1: sigma = power-iteration spectral norm ----------------
__global__ void k_sigma(const float* __restrict__ W, const float* __restrict__ u) {
    __shared__ float sv[DH];
    __shared__ float red[DH];
    int t = threadIdx.x;  // 512 threads

    float acc = 0.f;
    for (int i = 0; i < DH; i++) acc += W[(size_t)i * DH + t] * u[i];
    sv[t] = acc;
    red[t] = acc * acc;
    __syncthreads();
    for (int s = 256; s > 0; s >>= 1) {
        if (t < s) red[t] += red[t + s];
        __syncthreads();
    }
    float inv1 = 1.f / (sqrtf(red[0]) + 1e-12f);
    __syncthreads();
    sv[t] *= inv1;  // v
    __syncthreads();
    float sacc = 0.f;
    const float* wr = W + (size_t)t * DH;
    for (int j = 0; j < DH; j++) sacc += wr[j] * sv[j];
    red[t] = sacc * sacc;
    __syncthreads();
    for (int s = 256; s > 0; s >>= 1) {
        if (t < s) red[t] += red[t + s];
        __syncthreads();
    }
    if (t == 0) {
        float ss = red[0];
        g_sigma = ss / (sqrtf(ss) + 1e-12f);
    }
}

// ---------------- kernel 2: scaled/transposed weight prep ----------------
__global__ void k_prep(const float* __restrict__ W, const float* __restrict__ We,
                       const float* __restrict__ Wh) {
    float inv = 1.0f / g_sigma;
    int stride = gridDim.x * blockDim.x;
    int t0 = blockIdx.x * blockDim.x + threadIdx.x;
    for (int idx = t0; idx < DH * DH; idx += stride) {
        int k = idx >> 9, n = idx & 511;
        g_Wt[idx] = W[(size_t)n * DH + k] * inv;
    }
    for (int idx = t0; idx < DIN * DH; idx += stride) {
        int d = idx >> 9, j = idx & 511;
        g_Wet[idx] = We[(size_t)j * DIN + d];
    }
    for (int idx = t0; idx < DH * DOUT; idx += stride) {
        int k = idx / DOUT, o = idx - k * DOUT;
        g_Wht[idx] = Wh[(size_t)o * DH + k];
    }
}

// ---------------- generic tiled GEMM: C[M,N] = A[M,K] @ Bt[K,N] + bias ----------------
__global__ __launch_bounds__(256) void k_gemm(const float* __restrict__ A,
                                              const float* __restrict__ Bt,
                                              const float* __restrict__ bias,
                                              float* __restrict__ C, int M, int N, int K) {
    __shared__ float As[16][64];  // As[k][m]
    __shared__ float Bs[16][64];  // Bs[k][n]
    int tid = threadIdx.x;
    int bx = blockIdx.x;  // N tile
    int by = blockIdx.y;  // M tile
    int tx = tid & 15, ty = tid >> 4;
    float accv[4][4];
#pragma unroll
    for (int i = 0; i < 4; i++)
#pragma unroll
        for (int j = 0; j < 4; j++) accv[i][j] = 0.f;

    for (int k0 = 0; k0 < K; k0 += 16) {
        {
            int r = tid >> 2;
            int c = (tid & 3) * 4;
            float4 av = *(const float4*)&A[(size_t)(by * 64 + r) * K + k0 + c];
            As[c + 0][r] = av.x;
            As[c + 1][r] = av.y;
            As[c + 2][r] = av.z;
            As[c + 3][r] = av.w;
        }
        {
            int kr = tid >> 4;
            int c = (tid & 15) * 4;
            float4 bv = *(const float4*)&Bt[(size_t)(k0 + kr) * N + bx * 64 + c];
            *(float4*)&Bs[kr][c] = bv;
        }
        __syncthreads();
#pragma unroll
        for (int k = 0; k < 16; k++) {
            float a[4], b[4];
#pragma unroll
            for (int i = 0; i < 4; i++) a[i] = As[k][ty * 4 + i];
#pragma unroll
            for (int j = 0; j < 4; j++) b[j] = Bs[k][tx * 4 + j];
#pragma unroll
            for (int i = 0; i < 4; i++)
#pragma unroll
                for (int j = 0; j < 4; j++) accv[i][j] += a[i] * b[j];
        }
        __syncthreads();
    }
#pragma unroll
    for (int i = 0; i < 4; i++) {
        int m = by * 64 + ty * 4 + i;
#pragma unroll
        for (int j = 0; j < 4; j++) {
            int n = bx * 64 + tx * 4 + j;
            C[(size_t)m * N + n] = accv[i][j] + bias[n];
        }
    }
}

// ---------------- kernel 3: fused recurrent core ----------------
__device__ __forceinline__ void cp_chunk(const float* __restrict__ Wt, float* sh_w, int c,
                                         int buf, int tid) {
    const float4* src = (const float4*)(Wt + (size_t)c * KC * DH);
    unsigned sbase = (unsigned)__cvta_generic_to_shared(sh_w + (size_t)buf * KC * DH);
#pragma unroll
    for (int r = 0; r < 2; r++) {
        int e = tid + r * NT;  // float4 index within 8x512 chunk (1024 total)
        asm volatile("cp.async.cg.shared.global [%0], [%1], 16;" ::"r"(sbase + e * 16),
                     "l"(src + e));
    }
}

__global__ __launch_bounds__(NT, 1) void k_recurrent(const float* __restrict__ bW,
                                                     const int* __restrict__ steps_p) {
    extern __shared__ float smem[];
    float* sh_hh = smem;                 // MT*DH : inner state (matmul A operand)
    float* sh_xeb = smem + MT * DH;      // MT*DH : x_emb + bW
    float* sh_h = smem + 2 * MT * DH;    // MT*DH : outer state h
    float* sh_w = smem + 3 * MT * DH;    // 2*KC*DH double buffer

    const int tid = threadIdx.x;
    const int tm = tid >> 7;   // 0..3 (row group)
    const int tn = tid & 127;  // 0..127
    const int ncol0 = 2 * tn;  // + 256*j, j in {0,1}
    const int row0 = blockIdx.x * MT;
    const float* __restrict__ Wt = g_Wt;

    // load x_emb + bW tile, zero h
    for (int idx = tid; idx < MT * DH; idx += NT) {
        int n = idx & (DH - 1);
        sh_xeb[idx] = g_xemb[(size_t)row0 * DH + idx] + bW[n];
        sh_h[idx] = 0.f;
    }

    const float* hrow[8];
#pragma unroll
    for (int i = 0; i < 8; i++) hrow[i] = sh_hh + (size_t)(tm + 4 * i) * DH;

    const int steps = steps_p[0];
    __syncthreads();

    for (int s = 0; s < steps; s++) {
        // ---- inner iter 0 (hh starts at 0 => matmul term is 0) ----
#pragma unroll
        for (int i = 0; i < 8; i++) {
            const size_t rb = (size_t)(tm + 4 * i) * DH;
#pragma unroll
            for (int j = 0; j < 2; j++) {
                int n0 = ncol0 + 256 * j;
                float2 xe = *(const float2*)(sh_xeb + rb + n0);
                float2 hv = *(const float2*)(sh_h + rb + n0);
                float2 o;
                o.x = 0.5f * fast_tanh(hv.x + xe.x);
                o.y = 0.5f * fast_tanh(hv.y + xe.y);
                *(float2*)(sh_hh + rb + n0) = o;
            }
        }
        __syncthreads();

        // ---- inner iters 1..4 : hh = 0.5 hh + 0.5 tanh(hh@Wt + h + xeb) ----
        for (int it = 1; it < 5; it++) {
            ull acc2[8][2];
#pragma unroll
            for (int i = 0; i < 8; i++) {
                acc2[i][0] = 0ull;
                acc2[i][1] = 0ull;
            }

            cp_chunk(Wt, sh_w, 0, 0, tid);
            asm volatile("cp.async.commit_group;" ::: "memory");

            for (int c = 0; c < NCHUNK; c++) {
                asm volatile("cp.async.wait_group 0;" ::: "memory");
                __syncthreads();
                if (c + 1 < NCHUNK) {
                    cp_chunk(Wt, sh_w, c + 1, (c + 1) & 1, tid);
                    asm volatile("cp.async.commit_group;" ::: "memory");
                }
                const float* wb = sh_w + (size_t)(c & 1) * KC * DH;
                const int k0 = c * KC;
#pragma unroll
                for (int kk = 0; kk < KC; kk += 2) {
                    float2 a2v[8];
#pragma unroll
                    for (int i = 0; i < 8; i++)
                        a2v[i] = *(const float2*)(hrow[i] + k0 + kk);
#pragma unroll
                    for (int q = 0; q < 2; q++) {
                        const float* wrow = wb + (kk + q) * DH;
                        ull w0 = *(const ull*)(wrow + ncol0);
                        ull w1 = *(const ull*)(wrow + ncol0 + 256);
#pragma unroll
                        for (int i = 0; i < 8; i++) {
                            float av = q ? a2v[i].y : a2v[i].x;
                            ull a2 = pk2(av, av);
                            acc2[i][0] = fma2(a2, w0, acc2[i][0]);
                            acc2[i][1] = fma2(a2, w1, acc2[i][1]);
                        }
                    }
                }
            }
            __syncthreads();  // all matmul reads of sh_hh complete

            // elementwise update of hh
#pragma unroll
            for (int i = 0; i < 8; i++) {
                const size_t rb = (size_t)(tm + 4 * i) * DH;
#pragma unroll
                for (int j = 0; j < 2; j++) {
                    int n0 = ncol0 + 256 * j;
                    float ax, ay;
                    upk2(acc2[i][j], ax, ay);
                    float2 xe = *(const float2*)(sh_xeb + rb + n0);
                    float2 hv = *(const float2*)(sh_h + rb + n0);
                    float2 old = *(const float2*)(sh_hh + rb + n0);
                    float2 nv;
                    nv.x = 0.5f * old.x + 0.5f * fast_tanh(ax + hv.x + xe.x);
                    nv.y = 0.5f * old.y + 0.5f * fast_tanh(ay + hv.y + xe.y);
                    *(float2*)(sh_hh + rb + n0) = nv;
                }
            }
            __syncthreads();  // hh visible for next matmul
        }

        // ---- outer update: h = 0.5 h + 0.5 hh ----
#pragma unroll
        for (int i = 0; i < 8; i++) {
            const size_t rb = (size_t)(tm + 4 * i) * DH;
#pragma unroll
            for (int j = 0; j < 2; j++) {
                int n0 = ncol0 + 256 * j;
                float2 hh = *(const float2*)(sh_hh + rb + n0);
                float2 hv = *(const float2*)(sh_h + rb + n0);
                hv.x = 0.5f * hv.x + 0.5f * hh.x;
                hv.y = 0.5f * hv.y + 0.5f * hh.y;
                *(float2*)(sh_h + rb + n0) = hv;
            }
        }
        __syncthreads();
    }

    // store final h
#pragma unroll
    for (int i = 0; i < 8; i++) {
        int m = row0 + tm + 4 * i;
        const size_t rb = (size_t)(tm + 4 * i) * DH;
#pragma unroll
        for (int j = 0; j < 2; j++) {
            int n0 = ncol0 + 256 * j;
            float2 hv = *(const float2*)(sh_h + rb + n0);
            *(float2*)&g_h[(size_t)m * DH + n0] = hv;
        }
    }
}

// ---------------- launch ----------------
extern "C" void kernel_launch(void* const* d_in, const int* in_sizes, int n_in, void* d_out,
                              int out_size) {
    const float* x = (const float*)d_in[0];
    const float* We = (const float*)d_in[1];
    const float* be = (const float*)d_in[2];
    const float* W = (const float*)d_in[3];
    const float* bW = (const float*)d_in[4];
    const float* u = (const float*)d_in[5];
    const float* Wh = (const float*)d_in[6];
    const float* bh = (const float*)d_in[7];
    const int* steps = (const int*)d_in[8];
    float* out = (float*)d_out;

    float *p_Wet, *p_Wht, *p_xemb, *p_h;
    cudaGetSymbolAddress((void**)&p_Wet, g_Wet);
    cudaGetSymbolAddress((void**)&p_Wht, g_Wht);
    cudaGetSymbolAddress((void**)&p_xemb, g_xemb);
    cudaGetSymbolAddress((void**)&p_h, g_h);

    cudaFuncSetAttribute(k_recurrent, cudaFuncAttributeMaxDynamicSharedMemorySize,
                         REC_SMEM_BYTES);

    k_sigma<<<1, 512>>>(W, u);
    k_prep<<<512, 256>>>(W, We, Wh);

    dim3 g1(DH / 64, NB / 64);
    k_gemm<<<g1, 256>>>(x, p_Wet, be, p_xemb, NB, DH, DIN);

    k_recurrent<<<NB / MT, NT, REC_SMEM_BYTES>>>(bW, steps);

    dim3 g2(DOUT / 64, NB / 64);
    k_gemm<<<g2, 256>>>(p_h, p_Wht, bh, out, NB, DOUT, DH);
}

// round 9
// speedup vs baseline: 1.5706x; 1.5706x over previous
#include <cuda_runtime.h>
#include <cuda_bf16.h>
#include <cstdint>

#define DIN  1024
#define DH   512
#define NB   8192
#define DOUT 512

#define MROW 64
#define NCTA (NB / MROW)   // 128
#define NT   512           // 16 warps
#define NCHK 32            // K/16 chunks per matmul

// A (hh hi/lo) smem: 64 rows, pitch 1040B (65*16B -> ldmatrix conflict-free)
#define APITCH 1040
#define A_BYTES (MROW * APITCH)          // 66560
#define AHI_OFF 0
#define ALO_OFF A_BYTES                  // 66560
// W chunk buffers: 512 n-rows, pitch 48B (3*16B -> conflict-free), hi+lo
#define WPITCH 48
#define WCH_BYTES (DH * WPITCH)          // 24576
#define W_OFF (2 * A_BYTES)              // 133120
#define WBUF_STRIDE (2 * WCH_BYTES)      // 49152 (hi at +0, lo at +24576)
#define REC_SMEM (W_OFF + 2 * WBUF_STRIDE)  // 231424

typedef unsigned long long ull;

// ---------------- device scratch ----------------
__device__ float g_sigma;
__device__ __align__(16) float g_Wet[DIN * DH];
__device__ __align__(16) float g_Wht[DH * DOUT];
__device__ __align__(16) float g_bcomb[DH];
__device__ __align__(16) float g_xe[NB * DH];    // x@We.T + be + bW
__device__ __align__(16) float g_hxe[NB * DH];   // h + xe
__device__ __align__(16) float g_h[NB * DH];     // outer state
__device__ __align__(16) __nv_bfloat16 g_whi[DH * DH];  // (W/sigma)[n][k] hi
__device__ __align__(16) __nv_bfloat16 g_wlo[DH * DH];  // residual lo

// ---------------- helpers ----------------
__device__ __forceinline__ uint32_t smem_u32(const void* p) {
    uint32_t a;
    asm("{ .reg .u64 t; cvta.to.shared.u64 t, %1; cvt.u32.u64 %0, t; }" : "=r"(a) : "l"(p));
    return a;
}
__device__ __forceinline__ void cp16(uint32_t dst, const void* src) {
    asm volatile("cp.async.cg.shared.global [%0], [%1], 16;" ::"r"(dst), "l"(src));
}
__device__ __forceinline__ void cp_commit() {
    asm volatile("cp.async.commit_group;" ::: "memory");
}
__device__ __forceinline__ void cp_wait0() {
    asm volatile("cp.async.wait_group 0;" ::: "memory");
}
__device__ __forceinline__ void ldsm4(uint32_t* r, uint32_t addr) {
    asm volatile("ldmatrix.sync.aligned.m8n8.x4.shared.b16 {%0,%1,%2,%3}, [%4];"
                 : "=r"(r[0]), "=r"(r[1]), "=r"(r[2]), "=r"(r[3])
                 : "r"(addr));
}
__device__ __forceinline__ void mma16816(float* d, const uint32_t* a, const uint32_t* b) {
    asm volatile(
        "mma.sync.aligned.m16n8k16.row.col.f32.bf16.bf16.f32 "
        "{%0,%1,%2,%3}, {%4,%5,%6,%7}, {%8,%9}, {%0,%1,%2,%3};"
        : "+f"(d[0]), "+f"(d[1]), "+f"(d[2]), "+f"(d[3])
        : "r"(a[0]), "r"(a[1]), "r"(a[2]), "r"(a[3]), "r"(b[0]), "r"(b[1]));
}
__device__ __forceinline__ float fast_tanh(float x) {
    float a = fabsf(x);
    float e = exp2f(-2.8853900817779268f * a);
    float r = __fdividef(1.0f - e, 1.0f + e);
    return copysignf(r, x);
}
__device__ __forceinline__ uint32_t pack_bf2(float a, float b) {
    __nv_bfloat162 h;
    h.x = __float2bfloat16_rn(a);
    h.y = __float2bfloat16_rn(b);
    return *(uint32_t*)&h;
}
__device__ __forceinline__ float2 bf2f(uint32_t u) {
    __nv_bfloat162 h = *(__nv_bfloat162*)&u;
    return make_float2(__bfloat162float(h.x), __bfloat162float(h.y));
}

// ---------------- kernel 1: sigma ----------------
__global__ void k_sigma(const float* __restrict__ W, const float* __restrict__ u) {
    __shared__ float sv[DH];
    __shared__ float red[DH];
    int t = threadIdx.x;
    float acc = 0.f;
    for (int i = 0; i < DH; i++) acc += W[(size_t)i * DH + t] * u[i];
    sv[t] = acc;
    red[t] = acc * acc;
    __syncthreads();
    for (int s = 256; s > 0; s >>= 1) {
        if (t < s) red[t] += red[t + s];
        __syncthreads();
    }
    float inv1 = 1.f / (sqrtf(red[0]) + 1e-12f);
    __syncthreads();
    sv[t] *= inv1;
    __syncthreads();
    float sacc = 0.f;
    const float* wr = W + (size_t)t * DH;
    for (int j = 0; j < DH; j++) sacc += wr[j] * sv[j];
    red[t] = sacc * sacc;
    __syncthreads();
    for (int s = 256; s > 0; s >>= 1) {
        if (t < s) red[t] += red[t + s];
        __syncthreads();
    }
    if (t == 0) {
        float ss = red[0];
        g_sigma = ss / (sqrtf(ss) + 1e-12f);
    }
}

// ---------------- kernel 2: weight prep ----------------
__global__ void k_prep(const float* __restrict__ W, const float* __restrict__ We,
                       const float* __restrict__ Wh, const float* __restrict__ be,
                       const float* __restrict__ bW) {
    float inv = 1.0f / g_sigma;
    int stride = gridDim.x * blockDim.x;
    int t0 = blockIdx.x * blockDim.x + threadIdx.x;
    for (int idx = t0; idx < DH * DH; idx += stride) {
        float v = W[idx] * inv;
        __nv_bfloat16 hi = __float2bfloat16_rn(v);
        g_whi[idx] = hi;
        g_wlo[idx] = __float2bfloat16_rn(v - __bfloat162float(hi));
    }
    for (int idx = t0; idx < DIN * DH; idx += stride) {
        int d = idx >> 9, j = idx & 511;
        g_Wet[idx] = We[(size_t)j * DIN + d];
    }
    for (int idx = t0; idx < DH * DOUT; idx += stride) {
        int k = idx / DOUT, o = idx - k * DOUT;
        g_Wht[idx] = Wh[(size_t)o * DH + k];
    }
    for (int idx = t0; idx < DH; idx += stride) g_bcomb[idx] = be[idx] + bW[idx];
}

// ---------------- generic tiled GEMM ----------------
__global__ __launch_bounds__(256) void k_gemm(const float* __restrict__ A,
                                              const float* __restrict__ Bt,
                                              const float* __restrict__ bias,
                                              float* __restrict__ C, int M, int N, int K) {
    __shared__ float As[16][64];
    __shared__ float Bs[16][64];
    int tid = threadIdx.x;
    int bx = blockIdx.x, by = blockIdx.y;
    int tx = tid & 15, ty = tid >> 4;
    float accv[4][4];
#pragma unroll
    for (int i = 0; i < 4; i++)
#pragma unroll
        for (int j = 0; j < 4; j++) accv[i][j] = 0.f;
    for (int k0 = 0; k0 < K; k0 += 16) {
        {
            int r = tid >> 2;
            int c = (tid & 3) * 4;
            float4 av = *(const float4*)&A[(size_t)(by * 64 + r) * K + k0 + c];
            As[c + 0][r] = av.x;
            As[c + 1][r] = av.y;
            As[c + 2][r] = av.z;
            As[c + 3][r] = av.w;
        }
        {
            int kr = tid >> 4;
            int c = (tid & 15) * 4;
            float4 bv = *(const float4*)&Bt[(size_t)(k0 + kr) * N + bx * 64 + c];
            *(float4*)&Bs[kr][c] = bv;
        }
        __syncthreads();
#pragma unroll
        for (int k = 0; k < 16; k++) {
            float a[4], b[4];
#pragma unroll
            for (int i = 0; i < 4; i++) a[i] = As[k][ty * 4 + i];
#pragma unroll
            for (int j = 0; j < 4; j++) b[j] = Bs[k][tx * 4 + j];
#pragma unroll
            for (int i = 0; i < 4; i++)
#pragma unroll
                for (int j = 0; j < 4; j++) accv[i][j] += a[i] * b[j];
        }
        __syncthreads();
    }
#pragma unroll
    for (int i = 0; i < 4; i++) {
        int m = by * 64 + ty * 4 + i;
#pragma unroll
        for (int j = 0; j < 4; j++) {
            int n = bx * 64 + tx * 4 + j;
            C[(size_t)m * N + n] = accv[i][j] + bias[n];
        }
    }
}

// ---------------- kernel 3: mma.sync recurrent core ----------------
__global__ __launch_bounds__(NT, 1) void k_rec(const int* __restrict__ steps_p) {
    extern __shared__ char smem[];
    const uint32_t sb = smem_u32(smem);
    const int tid = threadIdx.x;
    const int w = tid >> 5, l = tid & 31;
    const int p = w >> 3;        // m-pass: rows [p*32, p*32+32)
    const int nb = (w & 7) * 64; // warp n-base
    const int row0 = blockIdx.x * MROW;

    // linear mapping for elementwise phases: row lr, 64-col block lcb
    const int lr = tid >> 3;
    const int lcb = (tid & 7) * 64;
    const size_t lg = (size_t)(row0 + lr) * DH + lcb;
    const uint32_t la_h = sb + AHI_OFF + lr * APITCH + lcb * 2;
    const uint32_t la_l = sb + ALO_OFF + lr * APITCH + lcb * 2;

    // init: h = 0, hxe = xe
#pragma unroll
    for (int q = 0; q < 16; q++) {
        float4 xv = *(const float4*)(g_xe + lg + 4 * q);
        *(float4*)(g_hxe + lg + 4 * q) = xv;
        *(float4*)(g_h + lg + 4 * q) = make_float4(0.f, 0.f, 0.f, 0.f);
    }

    const int steps = steps_p[0];

    for (int s = 0; s < steps; s++) {
        // ---- inner iter 0: hh = 0.5*tanh(hxe), stored as hi/lo bf16 in smem ----
#pragma unroll
        for (int q = 0; q < 16; q++) {
            float4 xv = *(const float4*)(g_hxe + lg + 4 * q);
            float v0 = 0.5f * fast_tanh(xv.x);
            float v1 = 0.5f * fast_tanh(xv.y);
            float v2 = 0.5f * fast_tanh(xv.z);
            float v3 = 0.5f * fast_tanh(xv.w);
            uint2 hp, lp;
            hp.x = pack_bf2(v0, v1);
            hp.y = pack_bf2(v2, v3);
            float2 r0 = bf2f(hp.x), r1 = bf2f(hp.y);
            lp.x = pack_bf2(v0 - r0.x, v1 - r0.y);
            lp.y = pack_bf2(v2 - r1.x, v3 - r1.y);
            *(uint2*)(smem + (la_h - sb) + 8 * q) = hp;
            *(uint2*)(smem + (la_l - sb) + 8 * q) = lp;
        }
        __syncthreads();

        // ---- inner iters 1..4 ----
        for (int it = 1; it < 5; it++) {
            float acc[2][8][4];
#pragma unroll
            for (int mt = 0; mt < 2; mt++)
#pragma unroll
                for (int nt = 0; nt < 8; nt++)
#pragma unroll
                    for (int e = 0; e < 4; e++) acc[mt][nt][e] = 0.f;

            // prefetch chunk 0 (thread t loads W row n=t, 32B hi + 32B lo)
            {
                uint32_t wb = sb + W_OFF;
                const __nv_bfloat16* sh = g_whi + (size_t)tid * DH;
                const __nv_bfloat16* sl = g_wlo + (size_t)tid * DH;
                cp16(wb + tid * WPITCH, sh);
                cp16(wb + tid * WPITCH + 16, sh + 8);
                cp16(wb + WCH_BYTES + tid * WPITCH, sl);
                cp16(wb + WCH_BYTES + tid * WPITCH + 16, sl + 8);
                cp_commit();
            }

            for (int c = 0; c < NCHK; c++) {
                cp_wait0();
                __syncthreads();  // chunk c ready; all warps done reading chunk c-1
                if (c + 1 < NCHK) {
                    uint32_t wb = sb + W_OFF + (uint32_t)((c + 1) & 1) * WBUF_STRIDE;
                    const __nv_bfloat16* sh = g_whi + (size_t)tid * DH + (c + 1) * 16;
                    const __nv_bfloat16* sl = g_wlo + (size_t)tid * DH + (c + 1) * 16;
                    cp16(wb + tid * WPITCH, sh);
                    cp16(wb + tid * WPITCH + 16, sh + 8);
                    cp16(wb + WCH_BYTES + tid * WPITCH, sl);
                    cp16(wb + WCH_BYTES + tid * WPITCH + 16, sl + 8);
                    cp_commit();
                }
                // A fragments: rows p*32 + mt*16, k = c*16
                uint32_t ah[2][4], al[2][4];
#pragma unroll
                for (int mt = 0; mt < 2; mt++) {
                    uint32_t ao = (uint32_t)((p * 32 + mt * 16 + (l & 15)) * APITCH +
                                             c * 32 + (l >> 4) * 16);
                    ldsm4(ah[mt], sb + AHI_OFF + ao);
                    ldsm4(al[mt], sb + ALO_OFF + ao);
                }
                // B fragments + MMAs, 2 ntiles at a time
                uint32_t wb = sb + W_OFF + (uint32_t)(c & 1) * WBUF_STRIDE;
#pragma unroll
                for (int nt2 = 0; nt2 < 4; nt2++) {
                    uint32_t bo = (uint32_t)((nb + nt2 * 16 + (l & 7) + 8 * (l >> 4)) *
                                                 WPITCH +
                                             ((l >> 3) & 1) * 16);
                    uint32_t bh[4], bl[4];
                    ldsm4(bh, wb + bo);
                    ldsm4(bl, wb + WCH_BYTES + bo);
#pragma unroll
                    for (int mt = 0; mt < 2; mt++) {
                        mma16816(acc[mt][2 * nt2 + 0], ah[mt], bh + 0);
                        mma16816(acc[mt][2 * nt2 + 1], ah[mt], bh + 2);
                        mma16816(acc[mt][2 * nt2 + 0], al[mt], bh + 0);
                        mma16816(acc[mt][2 * nt2 + 1], al[mt], bh + 2);
                        mma16816(acc[mt][2 * nt2 + 0], ah[mt], bl + 0);
                        mma16816(acc[mt][2 * nt2 + 1], ah[mt], bl + 2);
                    }
                }
            }
            __syncthreads();  // all A-smem reads done before epilogue writes

            // ---- epilogue: hh = 0.5*(hi+lo) + 0.5*tanh(acc + hxe) ----
#pragma unroll
            for (int mt = 0; mt < 2; mt++) {
                int ra = p * 32 + mt * 16 + (l >> 2);
#pragma unroll
                for (int half = 0; half < 2; half++) {
                    int r = ra + 8 * half;
                    const size_t gr = (size_t)(row0 + r) * DH;
                    uint32_t aoff = (uint32_t)(r * APITCH);
#pragma unroll
                    for (int nt = 0; nt < 8; nt++) {
                        int col = nb + nt * 8 + 2 * (l & 3);
                        uint32_t hu = *(uint32_t*)(smem + AHI_OFF + aoff + col * 2);
                        uint32_t lu = *(uint32_t*)(smem + ALO_OFF + aoff + col * 2);
                        float2 hf = bf2f(hu), lf = bf2f(lu);
                        float2 xe2 = *(const float2*)(g_hxe + gr + col);
                        float a0 = acc[mt][nt][2 * half + 0];
                        float a1 = acc[mt][nt][2 * half + 1];
                        float v0 = 0.5f * (hf.x + lf.x) + 0.5f * fast_tanh(a0 + xe2.x);
                        float v1 = 0.5f * (hf.y + lf.y) + 0.5f * fast_tanh(a1 + xe2.y);
                        uint32_t nh = pack_bf2(v0, v1);
                        float2 rr = bf2f(nh);
                        uint32_t nl = pack_bf2(v0 - rr.x, v1 - rr.y);
                        *(uint32_t*)(smem + AHI_OFF + aoff + col * 2) = nh;
                        *(uint32_t*)(smem + ALO_OFF + aoff + col * 2) = nl;
                    }
                }
            }
            __syncthreads();
        }

        // ---- outer update: h = 0.5h + 0.5hh ; hxe = h + xe ----
#pragma unroll
        for (int q = 0; q < 16; q++) {
            uint2 hp = *(uint2*)(smem + (la_h - sb) + 8 * q);
            uint2 lp = *(uint2*)(smem + (la_l - sb) + 8 * q);
            float2 h0 = bf2f(hp.x), h1 = bf2f(hp.y);
            float2 l0 = bf2f(lp.x), l1 = bf2f(lp.y);
            float4 hv = *(const float4*)(g_h + lg + 4 * q);
            float4 xv = *(const float4*)(g_xe + lg + 4 * q);
            float4 hn;
            hn.x = 0.5f * hv.x + 0.5f * (h0.x + l0.x);
            hn.y = 0.5f * hv.y + 0.5f * (h0.y + l0.y);
            hn.z = 0.5f * hv.z + 0.5f * (h1.x + l1.x);
            hn.w = 0.5f * hv.w + 0.5f * (h1.y + l1.y);
            *(float4*)(g_h + lg + 4 * q) = hn;
            float4 hx;
            hx.x = hn.x + xv.x;
            hx.y = hn.y + xv.y;
            hx.z = hn.z + xv.z;
            hx.w = hn.w + xv.w;
            *(float4*)(g_hxe + lg + 4 * q) = hx;
        }
        __syncthreads();
    }
}

// ---------------- launch ----------------
extern "C" void kernel_launch(void* const* d_in, const int* in_sizes, int n_in, void* d_out,
                              int out_size) {
    const float* x = (const float*)d_in[0];
    const float* We = (const float*)d_in[1];
    const float* be = (const float*)d_in[2];
    const float* W = (const float*)d_in[3];
    const float* bW = (const float*)d_in[4];
    const float* u = (const float*)d_in[5];
    const float* Wh = (const float*)d_in[6];
    const float* bh = (const float*)d_in[7];
    const int* steps = (const int*)d_in[8];
    float* out = (float*)d_out;

    float *p_Wet, *p_Wht, *p_xe, *p_h, *p_bcomb;
    cudaGetSymbolAddress((void**)&p_Wet, g_Wet);
    cudaGetSymbolAddress((void**)&p_Wht, g_Wht);
    cudaGetSymbolAddress((void**)&p_xe, g_xe);
    cudaGetSymbolAddress((void**)&p_h, g_h);
    cudaGetSymbolAddress((void**)&p_bcomb, g_bcomb);

    cudaFuncSetAttribute(k_rec, cudaFuncAttributeMaxDynamicSharedMemorySize, REC_SMEM);

    k_sigma<<<1, 512>>>(W, u);
    k_prep<<<512, 256>>>(W, We, Wh, be, bW);

    dim3 g1(DH / 64, NB / 64);
    k_gemm<<<g1, 256>>>(x, p_Wet, p_bcomb, p_xe, NB, DH, DIN);

    k_rec<<<NCTA, NT, REC_SMEM>>>(steps);

    dim3 g2(DOUT / 64, NB / 64);
    k_gemm<<<g2, 256>>>(p_h, p_Wht, bh, out, NB, DOUT, DH);
}

// round 10
// speedup vs baseline: 2.0071x; 1.2780x over previous
#include <cuda_runtime.h>
#include <cuda_bf16.h>
#include <cstdint>

#define DIN  1024
#define DH   512
#define NB   8192
#define DOUT 512

#define MROW 64
#define NCTA (NB / MROW)   // 128
#define NT   512           // 16 warps
#define NCHK 32            // K/16 chunks per matmul

// A (hh hi/lo) smem: 64 rows, pitch 1040B (65*16B -> ldmatrix conflict-free)
#define APITCH 1040
#define A_BYTES (MROW * APITCH)          // 66560
#define AHI_OFF 0
#define ALO_OFF A_BYTES                  // 66560
// B per-pair stages: 64 rows x 80B (hi k16 @+0..32, lo k16 @+32..64, pad 16)
#define BROW 80
#define BSTG (64 * BROW)                 // 5120 per stage
#define B_OFF (2 * A_BYTES)              // 133120
#define BPAIR (2 * BSTG)                 // 10240 (2 stages)
#define REC_SMEM (B_OFF + 8 * BPAIR)     // 215040

typedef unsigned long long ull;

// ---------------- device scratch ----------------
__device__ float g_sigma;
__device__ __align__(16) float g_Wet[DIN * DH];
__device__ __align__(16) float g_Wht[DH * DOUT];
__device__ __align__(16) float g_bcomb[DH];
__device__ __align__(16) float g_xe[NB * DH];    // x@We.T + be + bW
__device__ __align__(16) float g_hxe[NB * DH];   // h + xe
__device__ __align__(16) float g_h[NB * DH];     // outer state
__device__ __align__(16) __nv_bfloat16 g_whi[DH * DH];  // (W/sigma)[n][k] hi
__device__ __align__(16) __nv_bfloat16 g_wlo[DH * DH];  // residual lo

// ---------------- helpers ----------------
__device__ __forceinline__ uint32_t smem_u32(const void* p) {
    uint32_t a;
    asm("{ .reg .u64 t; cvta.to.shared.u64 t, %1; cvt.u32.u64 %0, t; }" : "=r"(a) : "l"(p));
    return a;
}
__device__ __forceinline__ void cp16(uint32_t dst, const void* src) {
    asm volatile("cp.async.cg.shared.global [%0], [%1], 16;" ::"r"(dst), "l"(src));
}
__device__ __forceinline__ void cp_commit() {
    asm volatile("cp.async.commit_group;" ::: "memory");
}
__device__ __forceinline__ void cp_wait0() {
    asm volatile("cp.async.wait_group 0;" ::: "memory");
}
__device__ __forceinline__ void cp_wait1() {
    asm volatile("cp.async.wait_group 1;" ::: "memory");
}
__device__ __forceinline__ void bar_pair(int id) {
    asm volatile("bar.sync %0, 64;" ::"r"(id) : "memory");
}
__device__ __forceinline__ void ldsm4(uint32_t* r, uint32_t addr) {
    asm volatile("ldmatrix.sync.aligned.m8n8.x4.shared.b16 {%0,%1,%2,%3}, [%4];"
                 : "=r"(r[0]), "=r"(r[1]), "=r"(r[2]), "=r"(r[3])
                 : "r"(addr));
}
__device__ __forceinline__ void mma16816(float* d, const uint32_t* a, const uint32_t* b) {
    asm volatile(
        "mma.sync.aligned.m16n8k16.row.col.f32.bf16.bf16.f32 "
        "{%0,%1,%2,%3}, {%4,%5,%6,%7}, {%8,%9}, {%0,%1,%2,%3};"
        : "+f"(d[0]), "+f"(d[1]), "+f"(d[2]), "+f"(d[3])
        : "r"(a[0]), "r"(a[1]), "r"(a[2]), "r"(a[3]), "r"(b[0]), "r"(b[1]));
}
__device__ __forceinline__ float fast_tanh(float x) {
    float a = fabsf(x);
    float e = exp2f(-2.8853900817779268f * a);
    float r = __fdividef(1.0f - e, 1.0f + e);
    return copysignf(r, x);
}
__device__ __forceinline__ uint32_t pack_bf2(float a, float b) {
    __nv_bfloat162 h;
    h.x = __float2bfloat16_rn(a);
    h.y = __float2bfloat16_rn(b);
    return *(uint32_t*)&h;
}
__device__ __forceinline__ float2 bf2f(uint32_t u) {
    __nv_bfloat162 h = *(__nv_bfloat162*)&u;
    return make_float2(__bfloat162float(h.x), __bfloat162float(h.y));
}

// ---------------- kernel 1: sigma ----------------
__global__ void k_sigma(const float* __restrict__ W, const float* __restrict__ u) {
    __shared__ float sv[DH];
    __shared__ float red[DH];
    int t = threadIdx.x;
    float acc = 0.f;
    for (int i = 0; i < DH; i++) acc += W[(size_t)i * DH + t] * u[i];
    sv[t] = acc;
    red[t] = acc * acc;
    __syncthreads();
    for (int s = 256; s > 0; s >>= 1) {
        if (t < s) red[t] += red[t + s];
        __syncthreads();
    }
    float inv1 = 1.f / (sqrtf(red[0]) + 1e-12f);
    __syncthreads();
    sv[t] *= inv1;
    __syncthreads();
    float sacc = 0.f;
    const float* wr = W + (size_t)t * DH;
    for (int j = 0; j < DH; j++) sacc += wr[j] * sv[j];
    red[t] = sacc * sacc;
    __syncthreads();
    for (int s = 256; s > 0; s >>= 1) {
        if (t < s) red[t] += red[t + s];
        __syncthreads();
    }
    if (t == 0) {
        float ss = red[0];
        g_sigma = ss / (sqrtf(ss) + 1e-12f);
    }
}

// ---------------- kernel 2: weight prep ----------------
__global__ void k_prep(const float* __restrict__ W, const float* __restrict__ We,
                       const float* __restrict__ Wh, const float* __restrict__ be,
                       const float* __restrict__ bW) {
    float inv = 1.0f / g_sigma;
    int stride = gridDim.x * blockDim.x;
    int t0 = blockIdx.x * blockDim.x + threadIdx.x;
    for (int idx = t0; idx < DH * DH; idx += stride) {
        float v = W[idx] * inv;
        __nv_bfloat16 hi = __float2bfloat16_rn(v);
        g_whi[idx] = hi;
        g_wlo[idx] = __float2bfloat16_rn(v - __bfloat162float(hi));
    }
    for (int idx = t0; idx < DIN * DH; idx += stride) {
        int d = idx >> 9, j = idx & 511;
        g_Wet[idx] = We[(size_t)j * DIN + d];
    }
    for (int idx = t0; idx < DH * DOUT; idx += stride) {
        int k = idx / DOUT, o = idx - k * DOUT;
        g_Wht[idx] = Wh[(size_t)o * DH + k];
    }
    for (int idx = t0; idx < DH; idx += stride) g_bcomb[idx] = be[idx] + bW[idx];
}

// ---------------- generic tiled GEMM ----------------
__global__ __launch_bounds__(256) void k_gemm(const float* __restrict__ A,
                                              const float* __restrict__ Bt,
                                              const float* __restrict__ bias,
                                              float* __restrict__ C, int M, int N, int K) {
    __shared__ float As[16][64];
    __shared__ float Bs[16][64];
    int tid = threadIdx.x;
    int bx = blockIdx.x, by = blockIdx.y;
    int tx = tid & 15, ty = tid >> 4;
    float accv[4][4];
#pragma unroll
    for (int i = 0; i < 4; i++)
#pragma unroll
        for (int j = 0; j < 4; j++) accv[i][j] = 0.f;
    for (int k0 = 0; k0 < K; k0 += 16) {
        {
            int r = tid >> 2;
            int c = (tid & 3) * 4;
            float4 av = *(const float4*)&A[(size_t)(by * 64 + r) * K + k0 + c];
            As[c + 0][r] = av.x;
            As[c + 1][r] = av.y;
            As[c + 2][r] = av.z;
            As[c + 3][r] = av.w;
        }
        {
            int kr = tid >> 4;
            int c = (tid & 15) * 4;
            float4 bv = *(const float4*)&Bt[(size_t)(k0 + kr) * N + bx * 64 + c];
            *(float4*)&Bs[kr][c] = bv;
        }
        __syncthreads();
#pragma unroll
        for (int k = 0; k < 16; k++) {
            float a[4], b[4];
#pragma unroll
            for (int i = 0; i < 4; i++) a[i] = As[k][ty * 4 + i];
#pragma unroll
            for (int j = 0; j < 4; j++) b[j] = Bs[k][tx * 4 + j];
#pragma unroll
            for (int i = 0; i < 4; i++)
#pragma unroll
                for (int j = 0; j < 4; j++) accv[i][j] += a[i] * b[j];
        }
        __syncthreads();
    }
#pragma unroll
    for (int i = 0; i < 4; i++) {
        int m = by * 64 + ty * 4 + i;
#pragma unroll
        for (int j = 0; j < 4; j++) {
            int n = bx * 64 + tx * 4 + j;
            C[(size_t)m * N + n] = accv[i][j] + bias[j + bx * 64];
        }
    }
}

// ---------------- kernel 3: mma.sync recurrent core ----------------
__global__ __launch_bounds__(NT, 1) void k_rec(const int* __restrict__ steps_p) {
    extern __shared__ char smem[];
    const uint32_t sb = smem_u32(smem);
    const int tid = threadIdx.x;
    const int w = tid >> 5, l = tid & 31;
    const int p = w >> 3;        // pair half: 0 -> loads rows 0-31, 1 -> rows 32-63
    const int g = w & 7;         // pair id
    const int nb = g * 64;       // warp n-base in W
    const int row0 = blockIdx.x * MROW;
    const uint32_t bbase = sb + B_OFF + (uint32_t)g * BPAIR;  // this pair's 2 stages

    // linear mapping for elementwise phases: row lr, 64-col block lcb
    const int lr = tid >> 3;
    const int lcb = (tid & 7) * 64;
    const size_t lg = (size_t)(row0 + lr) * DH + lcb;
    const uint32_t la_h = (uint32_t)(lr * APITCH + lcb * 2);
    const uint32_t la_l = la_h + ALO_OFF;

    // W loader source rows for this warp: row r = p*32 + l (local to pair's 64)
    const int wrow = p * 32 + l;
    const __nv_bfloat16* srch = g_whi + (size_t)(nb + wrow) * DH;
    const __nv_bfloat16* srcl = g_wlo + (size_t)(nb + wrow) * DH;
    const uint32_t bdst = (uint32_t)(wrow * BROW);

    // init: h = 0, hxe = xe
#pragma unroll
    for (int q = 0; q < 16; q++) {
        float4 xv = *(const float4*)(g_xe + lg + 4 * q);
        *(float4*)(g_hxe + lg + 4 * q) = xv;
        *(float4*)(g_h + lg + 4 * q) = make_float4(0.f, 0.f, 0.f, 0.f);
    }

    const int steps = steps_p[0];

    for (int s = 0; s < steps; s++) {
        // ---- inner iter 0: hh = 0.5*tanh(hxe) -> smem hi/lo ----
#pragma unroll
        for (int q = 0; q < 16; q++) {
            float4 xv = *(const float4*)(g_hxe + lg + 4 * q);
            float v0 = 0.5f * fast_tanh(xv.x);
            float v1 = 0.5f * fast_tanh(xv.y);
            float v2 = 0.5f * fast_tanh(xv.z);
            float v3 = 0.5f * fast_tanh(xv.w);
            uint2 hp, lp;
            hp.x = pack_bf2(v0, v1);
            hp.y = pack_bf2(v2, v3);
            float2 r0 = bf2f(hp.x), r1 = bf2f(hp.y);
            lp.x = pack_bf2(v0 - r0.x, v1 - r0.y);
            lp.y = pack_bf2(v2 - r1.x, v3 - r1.y);
            *(uint2*)(smem + la_h + 8 * q) = hp;
            *(uint2*)(smem + la_l + 8 * q) = lp;
        }
        __syncthreads();

        // ---- inner iters 1..4 ----
        for (int it = 1; it < 5; it++) {
            float acc[2][8][4];
#pragma unroll
            for (int mt = 0; mt < 2; mt++)
#pragma unroll
                for (int nt = 0; nt < 8; nt++)
#pragma unroll
                    for (int e = 0; e < 4; e++) acc[mt][nt][e] = 0.f;

            // prologue: this warp loads its rows for chunks 0,1
#pragma unroll
            for (int c0 = 0; c0 < 2; c0++) {
                uint32_t st = bbase + (uint32_t)c0 * BSTG + bdst;
                cp16(st + 0, srch + c0 * 16);
                cp16(st + 16, srch + c0 * 16 + 8);
                cp16(st + 32, srcl + c0 * 16);
                cp16(st + 48, srcl + c0 * 16 + 8);
                cp_commit();
            }
            cp_wait1();        // chunk 0 (own half) done
            bar_pair(1 + g);   // both halves of chunk 0 visible

            for (int c = 0; c < NCHK; c++) {
                const uint32_t stg = bbase + (uint32_t)(c & 1) * BSTG;
                // A fragments: rows p*32 + mt*16, k = c*16
                uint32_t ah[2][4], al[2][4];
#pragma unroll
                for (int mt = 0; mt < 2; mt++) {
                    uint32_t ao = (uint32_t)((p * 32 + mt * 16 + (l & 15)) * APITCH +
                                             c * 32 + (l >> 4) * 16);
                    ldsm4(ah[mt], sb + AHI_OFF + ao);
                    ldsm4(al[mt], sb + ALO_OFF + ao);
                }
#pragma unroll
                for (int nt2 = 0; nt2 < 4; nt2++) {
                    uint32_t bo = (uint32_t)((nt2 * 16 + (l & 7) + 8 * (l >> 4)) * BROW +
                                             ((l >> 3) & 1) * 16);
                    uint32_t bh[4], bl[4];
                    ldsm4(bh, stg + bo);
                    ldsm4(bl, stg + bo + 32);
#pragma unroll
                    for (int mt = 0; mt < 2; mt++) {
                        mma16816(acc[mt][2 * nt2 + 0], ah[mt], bh + 0);
                        mma16816(acc[mt][2 * nt2 + 1], ah[mt], bh + 2);
                        mma16816(acc[mt][2 * nt2 + 0], al[mt], bh + 0);
                        mma16816(acc[mt][2 * nt2 + 1], al[mt], bh + 2);
                        mma16816(acc[mt][2 * nt2 + 0], ah[mt], bl + 0);
                        mma16816(acc[mt][2 * nt2 + 1], ah[mt], bl + 2);
                    }
                }
                if (c + 1 < NCHK) {
                    bar_pair(1 + g);  // both warps done reading stage (c&1)
                    if (c + 2 < NCHK) {
                        uint32_t st = bbase + (uint32_t)(c & 1) * BSTG + bdst;
                        cp16(st + 0, srch + (c + 2) * 16);
                        cp16(st + 16, srch + (c + 2) * 16 + 8);
                        cp16(st + 32, srcl + (c + 2) * 16);
                        cp16(st + 48, srcl + (c + 2) * 16 + 8);
                        cp_commit();
                        cp_wait1();  // chunk c+1 (own half) done
                    } else {
                        cp_wait0();
                    }
                    bar_pair(1 + g);  // chunk c+1 fully visible
                }
            }
            __syncthreads();  // all A-smem reads done before epilogue writes

            // ---- epilogue: hh = 0.5*(hi+lo) + 0.5*tanh(acc + hxe) ----
#pragma unroll
            for (int mt = 0; mt < 2; mt++) {
                int ra = p * 32 + mt * 16 + (l >> 2);
#pragma unroll
                for (int half = 0; half < 2; half++) {
                    int r = ra + 8 * half;
                    const size_t gr = (size_t)(row0 + r) * DH;
                    uint32_t aoff = (uint32_t)(r * APITCH);
#pragma unroll
                    for (int nt = 0; nt < 8; nt++) {
                        int col = nb + nt * 8 + 2 * (l & 3);
                        uint32_t hu = *(uint32_t*)(smem + AHI_OFF + aoff + col * 2);
                        uint32_t lu = *(uint32_t*)(smem + ALO_OFF + aoff + col * 2);
                        float2 hf = bf2f(hu), lf = bf2f(lu);
                        float2 xe2 = *(const float2*)(g_hxe + gr + col);
                        float a0 = acc[mt][nt][2 * half + 0];
                        float a1 = acc[mt][nt][2 * half + 1];
                        float v0 = 0.5f * (hf.x + lf.x) + 0.5f * fast_tanh(a0 + xe2.x);
                        float v1 = 0.5f * (hf.y + lf.y) + 0.5f * fast_tanh(a1 + xe2.y);
                        uint32_t nh = pack_bf2(v0, v1);
                        float2 rr = bf2f(nh);
                        uint32_t nl = pack_bf2(v0 - rr.x, v1 - rr.y);
                        *(uint32_t*)(smem + AHI_OFF + aoff + col * 2) = nh;
                        *(uint32_t*)(smem + ALO_OFF + aoff + col * 2) = nl;
                    }
                }
            }
            __syncthreads();
        }

        // ---- outer update: h = 0.5h + 0.5hh ; hxe = h + xe ----
#pragma unroll
        for (int q = 0; q < 16; q++) {
            uint2 hp = *(uint2*)(smem + la_h + 8 * q);
            uint2 lp = *(uint2*)(smem + la_l + 8 * q);
            float2 h0 = bf2f(hp.x), h1 = bf2f(hp.y);
            float2 l0 = bf2f(lp.x), l1 = bf2f(lp.y);
            float4 hv = *(const float4*)(g_h + lg + 4 * q);
            float4 xv = *(const float4*)(g_xe + lg + 4 * q);
            float4 hn;
            hn.x = 0.5f * hv.x + 0.5f * (h0.x + l0.x);
            hn.y = 0.5f * hv.y + 0.5f * (h0.y + l0.y);
            hn.z = 0.5f * hv.z + 0.5f * (h1.x + l1.x);
            hn.w = 0.5f * hv.w + 0.5f * (h1.y + l1.y);
            *(float4*)(g_h + lg + 4 * q) = hn;
            float4 hx;
            hx.x = hn.x + xv.x;
            hx.y = hn.y + xv.y;
            hx.z = hn.z + xv.z;
            hx.w = hn.w + xv.w;
            *(float4*)(g_hxe + lg + 4 * q) = hx;
        }
        __syncthreads();
    }
}

// ---------------- launch ----------------
extern "C" void kernel_launch(void* const* d_in, const int* in_sizes, int n_in, void* d_out,
                              int out_size) {
    const float* x = (const float*)d_in[0];
    const float* We = (const float*)d_in[1];
    const float* be = (const float*)d_in[2];
    const float* W = (const float*)d_in[3];
    const float* bW = (const float*)d_in[4];
    const float* u = (const float*)d_in[5];
    const float* Wh = (const float*)d_in[6];
    const float* bh = (const float*)d_in[7];
    const int* steps = (const int*)d_in[8];
    float* out = (float*)d_out;

    float *p_Wet, *p_Wht, *p_xe, *p_h, *p_bcomb;
    cudaGetSymbolAddress((void**)&p_Wet, g_Wet);
    cudaGetSymbolAddress((void**)&p_Wht, g_Wht);
    cudaGetSymbolAddress((void**)&p_xe, g_xe);
    cudaGetSymbolAddress((void**)&p_h, g_h);
    cudaGetSymbolAddress((void**)&p_bcomb, g_bcomb);

    cudaFuncSetAttribute(k_rec, cudaFuncAttributeMaxDynamicSharedMemorySize, REC_SMEM);

    k_sigma<<<1, 512>>>(W, u);
    k_prep<<<512, 256>>>(W, We, Wh, be, bW);

    dim3 g1(DH / 64, NB / 64);
    k_gemm<<<g1, 256>>>(x, p_Wet, p_bcomb, p_xe, NB, DH, DIN);

    k_rec<<<NCTA, NT, REC_SMEM>>>(steps);

    dim3 g2(DOUT / 64, NB / 64);
    k_gemm<<<g2, 256>>>(p_h, p_Wht, bh, out, NB, DOUT, DH);
}

// round 11
// speedup vs baseline: 2.2999x; 1.1459x over previous
#include <cuda_runtime.h>
#include <cuda_fp16.h>
#include <cstdint>

#define DIN  1024
#define DH   512
#define NB   8192
#define DOUT 512

#define MROW 64
#define NCTA (NB / MROW)   // 128
#define NT   512           // 16 warps
#define NCHK 32            // K/16 chunks per matmul

// A (hh fp16) smem: 64 rows, pitch 1040B (65*16B -> ldmatrix conflict-free)
#define APITCH 1040
#define A_BYTES (MROW * APITCH)          // 66560
// B per-pair stages: 64 rows x 80B (hi k16 @+0..32, lo k16 @+32..64, pad 16)
#define BROW 80
#define BSTG (64 * BROW)                 // 5120 per stage
#define B_OFF A_BYTES                    // 66560
#define NBSTG 3
#define BPAIR (NBSTG * BSTG)             // 15360
#define REC_SMEM (B_OFF + 8 * BPAIR)     // 189440

typedef unsigned long long ull;

// ---------------- device scratch ----------------
__device__ float g_sigma;
__device__ __align__(16) float g_Wet[DIN * DH];
__device__ __align__(16) float g_Wht[DH * DOUT];
__device__ __align__(16) float g_bcomb[DH];
__device__ __align__(16) float g_xe[NB * DH];    // x@We.T + be + bW
__device__ __align__(16) float g_hxe[NB * DH];   // h + xe
__device__ __align__(16) float g_h[NB * DH];     // outer state
__device__ __align__(16) __half g_whi[DH * DH];  // (W/sigma)[n][k] fp16 hi
__device__ __align__(16) __half g_wlo[DH * DH];  // fp16 residual lo

// ---------------- helpers ----------------
__device__ __forceinline__ uint32_t smem_u32(const void* p) {
    uint32_t a;
    asm("{ .reg .u64 t; cvta.to.shared.u64 t, %1; cvt.u32.u64 %0, t; }" : "=r"(a) : "l"(p));
    return a;
}
__device__ __forceinline__ void cp16(uint32_t dst, const void* src) {
    asm volatile("cp.async.cg.shared.global [%0], [%1], 16;" ::"r"(dst), "l"(src));
}
__device__ __forceinline__ void cp_commit() {
    asm volatile("cp.async.commit_group;" ::: "memory");
}
__device__ __forceinline__ void cp_wait1() {
    asm volatile("cp.async.wait_group 1;" ::: "memory");
}
__device__ __forceinline__ void bar_pair(int id) {
    asm volatile("bar.sync %0, 64;" ::"r"(id) : "memory");
}
__device__ __forceinline__ void ldsm4(uint32_t* r, uint32_t addr) {
    asm volatile("ldmatrix.sync.aligned.m8n8.x4.shared.b16 {%0,%1,%2,%3}, [%4];"
                 : "=r"(r[0]), "=r"(r[1]), "=r"(r[2]), "=r"(r[3])
                 : "r"(addr));
}
__device__ __forceinline__ void mma16816(float* d, const uint32_t* a, const uint32_t* b) {
    asm volatile(
        "mma.sync.aligned.m16n8k16.row.col.f32.f16.f16.f32 "
        "{%0,%1,%2,%3}, {%4,%5,%6,%7}, {%8,%9}, {%0,%1,%2,%3};"
        : "+f"(d[0]), "+f"(d[1]), "+f"(d[2]), "+f"(d[3])
        : "r"(a[0]), "r"(a[1]), "r"(a[2]), "r"(a[3]), "r"(b[0]), "r"(b[1]));
}
__device__ __forceinline__ float fast_tanh(float x) {
    float a = fabsf(x);
    float e = exp2f(-2.8853900817779268f * a);
    float r = __fdividef(1.0f - e, 1.0f + e);
    return copysignf(r, x);
}
__device__ __forceinline__ uint32_t pack_h2(float a, float b) {
    __half2 h = __floats2half2_rn(a, b);
    return *(uint32_t*)&h;
}
__device__ __forceinline__ float2 h2f(uint32_t u) {
    __half2 h = *(__half2*)&u;
    return __half22float2(h);
}

// ---------------- kernel 1: sigma ----------------
__global__ void k_sigma(const float* __restrict__ W, const float* __restrict__ u) {
    __shared__ float sv[DH];
    __shared__ float red[DH];
    int t = threadIdx.x;
    float acc = 0.f;
    for (int i = 0; i < DH; i++) acc += W[(size_t)i * DH + t] * u[i];
    sv[t] = acc;
    red[t] = acc * acc;
    __syncthreads();
    for (int s = 256; s > 0; s >>= 1) {
        if (t < s) red[t] += red[t + s];
        __syncthreads();
    }
    float inv1 = 1.f / (sqrtf(red[0]) + 1e-12f);
    __syncthreads();
    sv[t] *= inv1;
    __syncthreads();
    float sacc = 0.f;
    const float* wr = W + (size_t)t * DH;
    for (int j = 0; j < DH; j++) sacc += wr[j] * sv[j];
    red[t] = sacc * sacc;
    __syncthreads();
    for (int s = 256; s > 0; s >>= 1) {
        if (t < s) red[t] += red[t + s];
        __syncthreads();
    }
    if (t == 0) {
        float ss = red[0];
        g_sigma = ss / (sqrtf(ss) + 1e-12f);
    }
}

// ---------------- kernel 2: weight prep ----------------
__global__ void k_prep(const float* __restrict__ W, const float* __restrict__ We,
                       const float* __restrict__ Wh, const float* __restrict__ be,
                       const float* __restrict__ bW) {
    float inv = 1.0f / g_sigma;
    int stride = gridDim.x * blockDim.x;
    int t0 = blockIdx.x * blockDim.x + threadIdx.x;
    for (int idx = t0; idx < DH * DH; idx += stride) {
        float v = W[idx] * inv;
        __half hi = __float2half_rn(v);
        g_whi[idx] = hi;
        g_wlo[idx] = __float2half_rn(v - __half2float(hi));
    }
    for (int idx = t0; idx < DIN * DH; idx += stride) {
        int d = idx >> 9, j = idx & 511;
        g_Wet[idx] = We[(size_t)j * DIN + d];
    }
    for (int idx = t0; idx < DH * DOUT; idx += stride) {
        int k = idx / DOUT, o = idx - k * DOUT;
        g_Wht[idx] = Wh[(size_t)o * DH + k];
    }
    for (int idx = t0; idx < DH; idx += stride) g_bcomb[idx] = be[idx] + bW[idx];
}

// ---------------- generic tiled GEMM ----------------
__global__ __launch_bounds__(256) void k_gemm(const float* __restrict__ A,
                                              const float* __restrict__ Bt,
                                              const float* __restrict__ bias,
                                              float* __restrict__ C, int M, int N, int K) {
    __shared__ float As[16][64];
    __shared__ float Bs[16][64];
    int tid = threadIdx.x;
    int bx = blockIdx.x, by = blockIdx.y;
    int tx = tid & 15, ty = tid >> 4;
    float accv[4][4];
#pragma unroll
    for (int i = 0; i < 4; i++)
#pragma unroll
        for (int j = 0; j < 4; j++) accv[i][j] = 0.f;
    for (int k0 = 0; k0 < K; k0 += 16) {
        {
            int r = tid >> 2;
            int c = (tid & 3) * 4;
            float4 av = *(const float4*)&A[(size_t)(by * 64 + r) * K + k0 + c];
            As[c + 0][r] = av.x;
            As[c + 1][r] = av.y;
            As[c + 2][r] = av.z;
            As[c + 3][r] = av.w;
        }
        {
            int kr = tid >> 4;
            int c = (tid & 15) * 4;
            float4 bv = *(const float4*)&Bt[(size_t)(k0 + kr) * N + bx * 64 + c];
            *(float4*)&Bs[kr][c] = bv;
        }
        __syncthreads();
#pragma unroll
        for (int k = 0; k < 16; k++) {
            float a[4], b[4];
#pragma unroll
            for (int i = 0; i < 4; i++) a[i] = As[k][ty * 4 + i];
#pragma unroll
            for (int j = 0; j < 4; j++) b[j] = Bs[k][tx * 4 + j];
#pragma unroll
            for (int i = 0; i < 4; i++)
#pragma unroll
                for (int j = 0; j < 4; j++) accv[i][j] += a[i] * b[j];
        }
        __syncthreads();
    }
#pragma unroll
    for (int i = 0; i < 4; i++) {
        int m = by * 64 + ty * 4 + i;
#pragma unroll
        for (int j = 0; j < 4; j++) {
            int n = bx * 64 + tx * 4 + j;
            C[(size_t)m * N + n] = accv[i][j] + bias[n];
        }
    }
}

// ---------------- kernel 3: mma.sync recurrent core (fp16 2-pass) ----------------
__global__ __launch_bounds__(NT, 1) void k_rec(const int* __restrict__ steps_p) {
    extern __shared__ char smem[];
    const uint32_t sb = smem_u32(smem);
    const int tid = threadIdx.x;
    const int w = tid >> 5, l = tid & 31;
    const int p = w >> 3;        // pair half
    const int g = w & 7;         // pair id
    const int nb = g * 64;       // warp n-base in W
    const int row0 = blockIdx.x * MROW;
    const uint32_t bbase = sb + B_OFF + (uint32_t)g * BPAIR;

    // linear mapping for elementwise phases: row lr, 64-col block lcb
    const int lr = tid >> 3;
    const int lcb = (tid & 7) * 64;
    const size_t lg = (size_t)(row0 + lr) * DH + lcb;
    const uint32_t la = (uint32_t)(lr * APITCH + lcb * 2);

    // W loader: this warp stages row wrow (local to pair's 64) of its chunk half
    const int wrow = p * 32 + l;
    const __half* srch = g_whi + (size_t)(nb + wrow) * DH;
    const __half* srcl = g_wlo + (size_t)(nb + wrow) * DH;
    const uint32_t bdst = (uint32_t)(wrow * BROW);

    // init: h = 0, hxe = xe
#pragma unroll
    for (int q = 0; q < 16; q++) {
        float4 xv = *(const float4*)(g_xe + lg + 4 * q);
        *(float4*)(g_hxe + lg + 4 * q) = xv;
        *(float4*)(g_h + lg + 4 * q) = make_float4(0.f, 0.f, 0.f, 0.f);
    }

    const int steps = steps_p[0];

    for (int s = 0; s < steps; s++) {
        // ---- inner iter 0: hh = 0.5*tanh(hxe) -> smem fp16 ----
#pragma unroll
        for (int q = 0; q < 16; q++) {
            float4 xv = *(const float4*)(g_hxe + lg + 4 * q);
            uint2 hp;
            hp.x = pack_h2(0.5f * fast_tanh(xv.x), 0.5f * fast_tanh(xv.y));
            hp.y = pack_h2(0.5f * fast_tanh(xv.z), 0.5f * fast_tanh(xv.w));
            *(uint2*)(smem + la + 8 * q) = hp;
        }
        __syncthreads();

        // ---- inner iters 1..4 ----
        for (int it = 1; it < 5; it++) {
            float acc[2][8][4];
#pragma unroll
            for (int mt = 0; mt < 2; mt++)
#pragma unroll
                for (int nt = 0; nt < 8; nt++)
#pragma unroll
                    for (int e = 0; e < 4; e++) acc[mt][nt][e] = 0.f;

            // prologue: chunks 0,1 into stages 0,1
#pragma unroll
            for (int c0 = 0; c0 < 2; c0++) {
                uint32_t st = bbase + (uint32_t)c0 * BSTG + bdst;
                cp16(st + 0, srch + c0 * 16);
                cp16(st + 16, srch + c0 * 16 + 8);
                cp16(st + 32, srcl + c0 * 16);
                cp16(st + 48, srcl + c0 * 16 + 8);
                cp_commit();
            }

            int stg_idx = 0;  // stage of chunk c
            for (int c = 0; c < NCHK; c++) {
                cp_wait1();       // own half of chunk c resident
                bar_pair(1 + g);  // both halves visible; partner done with chunk c-1
                // refill: chunk c+2 into stage (c+2)%3 (held chunk c-1)
                {
                    int c2 = c + 2;
                    if (c2 < NCHK) {
                        int s2 = stg_idx + 2;
                        if (s2 >= NBSTG) s2 -= NBSTG;
                        uint32_t st = bbase + (uint32_t)s2 * BSTG + bdst;
                        cp16(st + 0, srch + c2 * 16);
                        cp16(st + 16, srch + c2 * 16 + 8);
                        cp16(st + 32, srcl + c2 * 16);
                        cp16(st + 48, srcl + c2 * 16 + 8);
                    }
                    cp_commit();  // always commit (uniform group arithmetic)
                }
                const uint32_t stg = bbase + (uint32_t)stg_idx * BSTG;
                // A fragments (fp16 hh): rows p*32 + mt*16, k = c*16
                uint32_t ah[2][4];
#pragma unroll
                for (int mt = 0; mt < 2; mt++) {
                    uint32_t ao = (uint32_t)((p * 32 + mt * 16 + (l & 15)) * APITCH +
                                             c * 32 + (l >> 4) * 16);
                    ldsm4(ah[mt], sb + ao);
                }
#pragma unroll
                for (int nt2 = 0; nt2 < 4; nt2++) {
                    uint32_t bo = (uint32_t)((nt2 * 16 + (l & 7) + 8 * (l >> 4)) * BROW +
                                             ((l >> 3) & 1) * 16);
                    uint32_t bh[4], bl[4];
                    ldsm4(bh, stg + bo);
                    ldsm4(bl, stg + bo + 32);
#pragma unroll
                    for (int mt = 0; mt < 2; mt++) {
                        mma16816(acc[mt][2 * nt2 + 0], ah[mt], bh + 0);
                        mma16816(acc[mt][2 * nt2 + 1], ah[mt], bh + 2);
                        mma16816(acc[mt][2 * nt2 + 0], ah[mt], bl + 0);
                        mma16816(acc[mt][2 * nt2 + 1], ah[mt], bl + 2);
                    }
                }
                if (++stg_idx == NBSTG) stg_idx = 0;
            }
            __syncthreads();  // all A-smem reads done before epilogue writes

            // ---- epilogue: hh = 0.5*hh_old + 0.5*tanh(acc + hxe) ----
#pragma unroll
            for (int mt = 0; mt < 2; mt++) {
                int ra = p * 32 + mt * 16 + (l >> 2);
#pragma unroll
                for (int half = 0; half < 2; half++) {
                    int r = ra + 8 * half;
                    const size_t gr = (size_t)(row0 + r) * DH;
                    uint32_t aoff = (uint32_t)(r * APITCH);
#pragma unroll
                    for (int nt = 0; nt < 8; nt++) {
                        int col = nb + nt * 8 + 2 * (l & 3);
                        uint32_t hu = *(uint32_t*)(smem + aoff + col * 2);
                        float2 hf = h2f(hu);
                        float2 xe2 = *(const float2*)(g_hxe + gr + col);
                        float a0 = acc[mt][nt][2 * half + 0];
                        float a1 = acc[mt][nt][2 * half + 1];
                        float v0 = 0.5f * hf.x + 0.5f * fast_tanh(a0 + xe2.x);
                        float v1 = 0.5f * hf.y + 0.5f * fast_tanh(a1 + xe2.y);
                        *(uint32_t*)(smem + aoff + col * 2) = pack_h2(v0, v1);
                    }
                }
            }
            __syncthreads();
        }

        // ---- outer update: h = 0.5h + 0.5hh ; hxe = h + xe ----
#pragma unroll
        for (int q = 0; q < 16; q++) {
            uint2 hp = *(uint2*)(smem + la + 8 * q);
            float2 h0 = h2f(hp.x), h1 = h2f(hp.y);
            float4 hv = *(const float4*)(g_h + lg + 4 * q);
            float4 xv = *(const float4*)(g_xe + lg + 4 * q);
            float4 hn;
            hn.x = 0.5f * hv.x + 0.5f * h0.x;
            hn.y = 0.5f * hv.y + 0.5f * h0.y;
            hn.z = 0.5f * hv.z + 0.5f * h1.x;
            hn.w = 0.5f * hv.w + 0.5f * h1.y;
            *(float4*)(g_h + lg + 4 * q) = hn;
            float4 hx;
            hx.x = hn.x + xv.x;
            hx.y = hn.y + xv.y;
            hx.z = hn.z + xv.z;
            hx.w = hn.w + xv.w;
            *(float4*)(g_hxe + lg + 4 * q) = hx;
        }
        __syncthreads();
    }
}

// ---------------- launch ----------------
extern "C" void kernel_launch(void* const* d_in, const int* in_sizes, int n_in, void* d_out,
                              int out_size) {
    const float* x = (const float*)d_in[0];
    const float* We = (const float*)d_in[1];
    const float* be = (const float*)d_in[2];
    const float* W = (const float*)d_in[3];
    const float* bW = (const float*)d_in[4];
    const float* u = (const float*)d_in[5];
    const float* Wh = (const float*)d_in[6];
    const float* bh = (const float*)d_in[7];
    const int* steps = (const int*)d_in[8];
    float* out = (float*)d_out;

    float *p_Wet, *p_Wht, *p_xe, *p_h, *p_bcomb;
    cudaGetSymbolAddress((void**)&p_Wet, g_Wet);
    cudaGetSymbolAddress((void**)&p_Wht, g_Wht);
    cudaGetSymbolAddress((void**)&p_xe, g_xe);
    cudaGetSymbolAddress((void**)&p_h, g_h);
    cudaGetSymbolAddress((void**)&p_bcomb, g_bcomb);

    cudaFuncSetAttribute(k_rec, cudaFuncAttributeMaxDynamicSharedMemorySize, REC_SMEM);

    k_sigma<<<1, 512>>>(W, u);
    k_prep<<<512, 256>>>(W, We, Wh, be, bW);

    dim3 g1(DH / 64, NB / 64);
    k_gemm<<<g1, 256>>>(x, p_Wet, p_bcomb, p_xe, NB, DH, DIN);

    k_rec<<<NCTA, NT, REC_SMEM>>>(steps);

    dim3 g2(DOUT / 64, NB / 64);
    k_gemm<<<g2, 256>>>(p_h, p_Wht, bh, out, NB, DOUT, DH);
}

// round 12
// speedup vs baseline: 2.3055x; 1.0024x over previous
#include <cuda_runtime.h>
#include <cuda_fp16.h>
#include <cstdint>

#define DIN  1024
#define DH   512
#define NB   8192
#define DOUT 512

#define MROW 64
#define NCTA (NB / MROW)   // 128
#define NT   512           // 16 warps
#define NCHK 32            // K/16 chunks per matmul

// A (hh fp16) smem: 64 rows, pitch 1040B (65*16B -> ldmatrix conflict-free)
#define APITCH 1040
#define A_BYTES (MROW * APITCH)          // 66560
// B per-warp stages: 32 rows x 80B (hi k16 @+0..32, lo k16 @+32..64, pad 16)
#define BROW 80
#define BSTG (32 * BROW)                 // 2560 per stage
#define NBSTG 3
#define BWRP (NBSTG * BSTG)              // 7680 per warp
#define B_OFF A_BYTES                    // 66560
#define REC_SMEM (B_OFF + 16 * BWRP)     // 189440

typedef unsigned long long ull;

// ---------------- device scratch ----------------
__device__ float g_sigma;
__device__ __align__(16) float g_Wet[DIN * DH];
__device__ __align__(16) float g_Wht[DH * DOUT];
__device__ __align__(16) float g_bcomb[DH];
__device__ __align__(16) float g_xe[NB * DH];    // x@We.T + be + bW
__device__ __align__(16) float g_hxe[NB * DH];   // h + xe
__device__ __align__(16) float g_h[NB * DH];     // outer state
__device__ __align__(16) __half g_whi[DH * DH];  // (W/sigma)[n][k] fp16 hi
__device__ __align__(16) __half g_wlo[DH * DH];  // fp16 residual lo

// ---------------- helpers ----------------
__device__ __forceinline__ uint32_t smem_u32(const void* p) {
    uint32_t a;
    asm("{ .reg .u64 t; cvta.to.shared.u64 t, %1; cvt.u32.u64 %0, t; }" : "=r"(a) : "l"(p));
    return a;
}
__device__ __forceinline__ void cp16(uint32_t dst, const void* src) {
    asm volatile("cp.async.cg.shared.global [%0], [%1], 16;" ::"r"(dst), "l"(src));
}
__device__ __forceinline__ void cp_commit() {
    asm volatile("cp.async.commit_group;" ::: "memory");
}
__device__ __forceinline__ void cp_wait1() {
    asm volatile("cp.async.wait_group 1;" ::: "memory");
}
__device__ __forceinline__ void ldsm4(uint32_t* r, uint32_t addr) {
    asm volatile("ldmatrix.sync.aligned.m8n8.x4.shared.b16 {%0,%1,%2,%3}, [%4];"
                 : "=r"(r[0]), "=r"(r[1]), "=r"(r[2]), "=r"(r[3])
                 : "r"(addr));
}
__device__ __forceinline__ void mma16816(float* d, const uint32_t* a, const uint32_t* b) {
    asm volatile(
        "mma.sync.aligned.m16n8k16.row.col.f32.f16.f16.f32 "
        "{%0,%1,%2,%3}, {%4,%5,%6,%7}, {%8,%9}, {%0,%1,%2,%3};"
        : "+f"(d[0]), "+f"(d[1]), "+f"(d[2]), "+f"(d[3])
        : "r"(a[0]), "r"(a[1]), "r"(a[2]), "r"(a[3]), "r"(b[0]), "r"(b[1]));
}
__device__ __forceinline__ float fast_tanh(float x) {
    float a = fabsf(x);
    float e = exp2f(-2.8853900817779268f * a);
    float r = __fdividef(1.0f - e, 1.0f + e);
    return copysignf(r, x);
}
__device__ __forceinline__ uint32_t pack_h2(float a, float b) {
    __half2 h = __floats2half2_rn(a, b);
    return *(uint32_t*)&h;
}
__device__ __forceinline__ float2 h2f(uint32_t u) {
    __half2 h = *(__half2*)&u;
    return __half22float2(h);
}

// ---------------- kernel 1: sigma ----------------
__global__ void k_sigma(const float* __restrict__ W, const float* __restrict__ u) {
    __shared__ float sv[DH];
    __shared__ float red[DH];
    int t = threadIdx.x;
    float acc = 0.f;
    for (int i = 0; i < DH; i++) acc += W[(size_t)i * DH + t] * u[i];
    sv[t] = acc;
    red[t] = acc * acc;
    __syncthreads();
    for (int s = 256; s > 0; s >>= 1) {
        if (t < s) red[t] += red[t + s];
        __syncthreads();
    }
    float inv1 = 1.f / (sqrtf(red[0]) + 1e-12f);
    __syncthreads();
    sv[t] *= inv1;
    __syncthreads();
    float sacc = 0.f;
    const float* wr = W + (size_t)t * DH;
    for (int j = 0; j < DH; j++) sacc += wr[j] * sv[j];
    red[t] = sacc * sacc;
    __syncthreads();
    for (int s = 256; s > 0; s >>= 1) {
        if (t < s) red[t] += red[t + s];
        __syncthreads();
    }
    if (t == 0) {
        float ss = red[0];
        g_sigma = ss / (sqrtf(ss) + 1e-12f);
    }
}

// ---------------- kernel 2: weight prep ----------------
__global__ void k_prep(const float* __restrict__ W, const float* __restrict__ We,
                       const float* __restrict__ Wh, const float* __restrict__ be,
                       const float* __restrict__ bW) {
    float inv = 1.0f / g_sigma;
    int stride = gridDim.x * blockDim.x;
    int t0 = blockIdx.x * blockDim.x + threadIdx.x;
    for (int idx = t0; idx < DH * DH; idx += stride) {
        float v = W[idx] * inv;
        __half hi = __float2half_rn(v);
        g_whi[idx] = hi;
        g_wlo[idx] = __float2half_rn(v - __half2float(hi));
    }
    for (int idx = t0; idx < DIN * DH; idx += stride) {
        int d = idx >> 9, j = idx & 511;
        g_Wet[idx] = We[(size_t)j * DIN + d];
    }
    for (int idx = t0; idx < DH * DOUT; idx += stride) {
        int k = idx / DOUT, o = idx - k * DOUT;
        g_Wht[idx] = Wh[(size_t)o * DH + k];
    }
    for (int idx = t0; idx < DH; idx += stride) g_bcomb[idx] = be[idx] + bW[idx];
}

// ---------------- generic tiled GEMM ----------------
__global__ __launch_bounds__(256) void k_gemm(const float* __restrict__ A,
                                              const float* __restrict__ Bt,
                                              const float* __restrict__ bias,
                                              float* __restrict__ C, int M, int N, int K) {
    __shared__ float As[16][64];
    __shared__ float Bs[16][64];
    int tid = threadIdx.x;
    int bx = blockIdx.x, by = blockIdx.y;
    int tx = tid & 15, ty = tid >> 4;
    float accv[4][4];
#pragma unroll
    for (int i = 0; i < 4; i++)
#pragma unroll
        for (int j = 0; j < 4; j++) accv[i][j] = 0.f;
    for (int k0 = 0; k0 < K; k0 += 16) {
        {
            int r = tid >> 2;
            int c = (tid & 3) * 4;
            float4 av = *(const float4*)&A[(size_t)(by * 64 + r) * K + k0 + c];
            As[c + 0][r] = av.x;
            As[c + 1][r] = av.y;
            As[c + 2][r] = av.z;
            As[c + 3][r] = av.w;
        }
        {
            int kr = tid >> 4;
            int c = (tid & 15) * 4;
            float4 bv = *(const float4*)&Bt[(size_t)(k0 + kr) * N + bx * 64 + c];
            *(float4*)&Bs[kr][c] = bv;
        }
        __syncthreads();
#pragma unroll
        for (int k = 0; k < 16; k++) {
            float a[4], b[4];
#pragma unroll
            for (int i = 0; i < 4; i++) a[i] = As[k][ty * 4 + i];
#pragma unroll
            for (int j = 0; j < 4; j++) b[j] = Bs[k][tx * 4 + j];
#pragma unroll
            for (int i = 0; i < 4; i++)
#pragma unroll
                for (int j = 0; j < 4; j++) accv[i][j] += a[i] * b[j];
        }
        __syncthreads();
    }
#pragma unroll
    for (int i = 0; i < 4; i++) {
        int m = by * 64 + ty * 4 + i;
#pragma unroll
        for (int j = 0; j < 4; j++) {
            int n = bx * 64 + tx * 4 + j;
            C[(size_t)m * N + n] = accv[i][j] + bias[n];
        }
    }
}

// ---------------- kernel 3: mma.sync recurrent core (warp-private W pipe) ----------------
__global__ __launch_bounds__(NT, 1) void k_rec(const int* __restrict__ steps_p) {
    extern __shared__ char smem[];
    const uint32_t sb = smem_u32(smem);
    const int tid = threadIdx.x;
    const int w = tid >> 5, l = tid & 31;
    const int nb = w * 32;  // this warp's private n-range [nb, nb+32)
    const int row0 = blockIdx.x * MROW;
    const uint32_t bbase = sb + B_OFF + (uint32_t)w * BWRP;

    // linear mapping for elementwise phases: row lr, 64-col block lcb
    const int lr = tid >> 3;
    const int lcb = (tid & 7) * 64;
    const size_t lg = (size_t)(row0 + lr) * DH + lcb;
    const uint32_t la = (uint32_t)(lr * APITCH + lcb * 2);

    // W loader: lane l stages W row (nb + l)
    const __half* srch = g_whi + (size_t)(nb + l) * DH;
    const __half* srcl = g_wlo + (size_t)(nb + l) * DH;
    const uint32_t bdst = (uint32_t)(l * BROW);

    // init: h = 0, hxe = xe
#pragma unroll
    for (int q = 0; q < 16; q++) {
        float4 xv = *(const float4*)(g_xe + lg + 4 * q);
        *(float4*)(g_hxe + lg + 4 * q) = xv;
        *(float4*)(g_h + lg + 4 * q) = make_float4(0.f, 0.f, 0.f, 0.f);
    }

    const int steps = steps_p[0];

    for (int s = 0; s < steps; s++) {
        // ---- inner iter 0: hh = 0.5*tanh(hxe) -> smem fp16 ----
#pragma unroll
        for (int q = 0; q < 16; q++) {
            float4 xv = *(const float4*)(g_hxe + lg + 4 * q);
            uint2 hp;
            hp.x = pack_h2(0.5f * fast_tanh(xv.x), 0.5f * fast_tanh(xv.y));
            hp.y = pack_h2(0.5f * fast_tanh(xv.z), 0.5f * fast_tanh(xv.w));
            *(uint2*)(smem + la + 8 * q) = hp;
        }
        __syncthreads();

        // ---- inner iters 1..4 ----
        for (int it = 1; it < 5; it++) {
            float acc[4][4][4];
#pragma unroll
            for (int mt = 0; mt < 4; mt++)
#pragma unroll
                for (int nt = 0; nt < 4; nt++)
#pragma unroll
                    for (int e = 0; e < 4; e++) acc[mt][nt][e] = 0.f;

            // prologue: chunks 0,1 into stages 0,1 (warp-private)
#pragma unroll
            for (int c0 = 0; c0 < 2; c0++) {
                uint32_t st = bbase + (uint32_t)c0 * BSTG + bdst;
                cp16(st + 0, srch + c0 * 16);
                cp16(st + 16, srch + c0 * 16 + 8);
                cp16(st + 32, srcl + c0 * 16);
                cp16(st + 48, srcl + c0 * 16 + 8);
                cp_commit();
            }

            int stg_idx = 0;  // stage of chunk c
            for (int c = 0; c < NCHK; c++) {
                cp_wait1();  // own chunk c resident (warp-local, no barrier)
                // refill: chunk c+2 into stage (stg_idx+2)%3 (read at c-1, safe)
                {
                    int c2 = c + 2;
                    if (c2 < NCHK) {
                        int s2 = stg_idx + 2;
                        if (s2 >= NBSTG) s2 -= NBSTG;
                        uint32_t st = bbase + (uint32_t)s2 * BSTG + bdst;
                        cp16(st + 0, srch + c2 * 16);
                        cp16(st + 16, srch + c2 * 16 + 8);
                        cp16(st + 32, srcl + c2 * 16);
                        cp16(st + 48, srcl + c2 * 16 + 8);
                    }
                    cp_commit();  // uniform group arithmetic
                }
                const uint32_t stg = bbase + (uint32_t)stg_idx * BSTG;
                // A fragments (fp16 hh): rows mt*16, k = c*16
                uint32_t ah[4][4];
#pragma unroll
                for (int mt = 0; mt < 4; mt++) {
                    uint32_t ao = (uint32_t)((mt * 16 + (l & 15)) * APITCH + c * 32 +
                                             (l >> 4) * 16);
                    ldsm4(ah[mt], sb + ao);
                }
#pragma unroll
                for (int nt2 = 0; nt2 < 2; nt2++) {
                    uint32_t bo = (uint32_t)((nt2 * 16 + (l & 7) + 8 * (l >> 4)) * BROW +
                                             ((l >> 3) & 1) * 16);
                    uint32_t bh[4], bl[4];
                    ldsm4(bh, stg + bo);
                    ldsm4(bl, stg + bo + 32);
#pragma unroll
                    for (int mt = 0; mt < 4; mt++) {
                        mma16816(acc[mt][2 * nt2 + 0], ah[mt], bh + 0);
                        mma16816(acc[mt][2 * nt2 + 1], ah[mt], bh + 2);
                        mma16816(acc[mt][2 * nt2 + 0], ah[mt], bl + 0);
                        mma16816(acc[mt][2 * nt2 + 1], ah[mt], bl + 2);
                    }
                }
                if (++stg_idx == NBSTG) stg_idx = 0;
            }
            __syncthreads();  // all A-smem reads done before epilogue writes

            // ---- epilogue: hh = 0.5*hh_old + 0.5*tanh(acc + hxe) ----
#pragma unroll
            for (int mt = 0; mt < 4; mt++) {
                int ra = mt * 16 + (l >> 2);
#pragma unroll
                for (int half = 0; half < 2; half++) {
                    int r = ra + 8 * half;
                    const size_t gr = (size_t)(row0 + r) * DH;
                    uint32_t aoff = (uint32_t)(r * APITCH);
#pragma unroll
                    for (int nt = 0; nt < 4; nt++) {
                        int col = nb + nt * 8 + 2 * (l & 3);
                        uint32_t hu = *(uint32_t*)(smem + aoff + col * 2);
                        float2 hf = h2f(hu);
                        float2 xe2 = *(const float2*)(g_hxe + gr + col);
                        float a0 = acc[mt][nt][2 * half + 0];
                        float a1 = acc[mt][nt][2 * half + 1];
                        float v0 = 0.5f * hf.x + 0.5f * fast_tanh(a0 + xe2.x);
                        float v1 = 0.5f * hf.y + 0.5f * fast_tanh(a1 + xe2.y);
                        *(uint32_t*)(smem + aoff + col * 2) = pack_h2(v0, v1);
                    }
                }
            }
            __syncthreads();
        }

        // ---- outer update: h = 0.5h + 0.5hh ; hxe = h + xe ----
#pragma unroll
        for (int q = 0; q < 16; q++) {
            uint2 hp = *(uint2*)(smem + la + 8 * q);
            float2 h0 = h2f(hp.x), h1 = h2f(hp.y);
            float4 hv = *(const float4*)(g_h + lg + 4 * q);
            float4 xv = *(const float4*)(g_xe + lg + 4 * q);
            float4 hn;
            hn.x = 0.5f * hv.x + 0.5f * h0.x;
            hn.y = 0.5f * hv.y + 0.5f * h0.y;
            hn.z = 0.5f * hv.z + 0.5f * h1.x;
            hn.w = 0.5f * hv.w + 0.5f * h1.y;
            *(float4*)(g_h + lg + 4 * q) = hn;
            float4 hx;
            hx.x = hn.x + xv.x;
            hx.y = hn.y + xv.y;
            hx.z = hn.z + xv.z;
            hx.w = hn.w + xv.w;
            *(float4*)(g_hxe + lg + 4 * q) = hx;
        }
        __syncthreads();
    }
}

// ---------------- launch ----------------
extern "C" void kernel_launch(void* const* d_in, const int* in_sizes, int n_in, void* d_out,
                              int out_size) {
    const float* x = (const float*)d_in[0];
    const float* We = (const float*)d_in[1];
    const float* be = (const float*)d_in[2];
    const float* W = (const float*)d_in[3];
    const float* bW = (const float*)d_in[4];
    const float* u = (const float*)d_in[5];
    const float* Wh = (const float*)d_in[6];
    const float* bh = (const float*)d_in[7];
    const int* steps = (const int*)d_in[8];
    float* out = (float*)d_out;

    float *p_Wet, *p_Wht, *p_xe, *p_h, *p_bcomb;
    cudaGetSymbolAddress((void**)&p_Wet, g_Wet);
    cudaGetSymbolAddress((void**)&p_Wht, g_Wht);
    cudaGetSymbolAddress((void**)&p_xe, g_xe);
    cudaGetSymbolAddress((void**)&p_h, g_h);
    cudaGetSymbolAddress((void**)&p_bcomb, g_bcomb);

    cudaFuncSetAttribute(k_rec, cudaFuncAttributeMaxDynamicSharedMemorySize, REC_SMEM);

    k_sigma<<<1, 512>>>(W, u);
    k_prep<<<512, 256>>>(W, We, Wh, be, bW);

    dim3 g1(DH / 64, NB / 64);
    k_gemm<<<g1, 256>>>(x, p_Wet, p_bcomb, p_xe, NB, DH, DIN);

    k_rec<<<NCTA, NT, REC_SMEM>>>(steps);

    dim3 g2(DOUT / 64, NB / 64);
    k_gemm<<<g2, 256>>>(p_h, p_Wht, bh, out, NB, DOUT, DH);
}